// round 9
// baseline (speedup 1.0000x reference)
#include <cuda_runtime.h>
#include <cstdint>

#define Bv 4
#define Nv 512
#define Dv 256
#define Lv 64

typedef unsigned long long ull;

// Scratch for projected+weighted features, layout [b][l][n]  (512 KB)
__device__ float g_xh[Bv * Lv * Nv];
// Device-wide barrier state (replay-safe: count resets, release monotone)
__device__ unsigned g_count = 0;
__device__ unsigned g_release = 0;

// ---------------------------------------------------------------------------
// Packed f32x2 helpers (sm_103a)
// ---------------------------------------------------------------------------
__device__ __forceinline__ ull pk2(float a) {
    ull r;
    asm("mov.b64 %0, {%1, %2};" : "=l"(r) : "f"(a), "f"(a));
    return r;
}
__device__ __forceinline__ ull add2(ull a, ull b) {
    ull r;
    asm("add.rn.f32x2 %0, %1, %2;" : "=l"(r) : "l"(a), "l"(b));
    return r;
}
__device__ __forceinline__ float lo2(ull a) {
    float x, y;
    asm("mov.b64 {%0, %1}, %2;" : "=f"(x), "=f"(y) : "l"(a));
    return x;
}
__device__ __forceinline__ float hi2(ull a) {
    float x, y;
    asm("mov.b64 {%0, %1}, %2;" : "=f"(x), "=f"(y) : "l"(a));
    return y;
}

// ---------------------------------------------------------------------------
// Fused kernel. Grid 128 = (b, 16-row i-tile), 1024 threads, ~205 KB smem.
// Weights folded into projection (learn_w >= 0).
// Smem (floats): sj[32768] | si2(2048) | psum[8192] | adjs[8192] | red[128]
// ---------------------------------------------------------------------------
__global__ __launch_bounds__(1024, 1) void fused_kernel(
    const float* __restrict__ x, const float* __restrict__ adj,
    const float* __restrict__ W, const float* __restrict__ lw,
    float* __restrict__ out) {
    extern __shared__ float sm[];
    float* sj   = sm;                              // [64][512]
    ull*   si2  = (ull*)(sm + 32768);              // [64][16] {-wv,-wv}
    float* psum = sm + 32768 + 2048;               // [16][512]
    float* adjs = psum + 8192;                     // [16][512] adj tile
    float* red  = adjs + 8192;                     // [2][16][2]
    // Phase-A aliases (dead during phase A)
    float* Wt = sm;                                // [256][68] in sj area
    float* xs = psum;                              // [256][17] in psum area

    int b  = blockIdx.x >> 5;
    int i0 = (blockIdx.x & 31) << 4;
    int tid = threadIdx.x;

    // ---- adj tile prefetch (independent; overlaps phase A + barrier) ------
    {
        const float4* asrc = (const float4*)(adj + (size_t)(b * Nv + i0) * Nv);
        float4* adst = (float4*)adjs;
#pragma unroll
        for (int k = 0; k < 2; ++k)
            adst[tid + k * 1024] = asrc[tid + k * 1024];
    }

    // ---------------- Phase A: weighted projection of this block's 16 rows -
    for (int idx = tid; idx < 16 * 256; idx += 1024) {
        int rr = idx >> 8, d = idx & 255;
        xs[d * 17 + rr] = x[(b * Nv + i0 + rr) * Dv + d];
    }
    for (int idx = tid; idx < 64 * 256; idx += 1024) {
        int l = idx >> 8, d = idx & 255;
        Wt[d * 68 + l] = W[l * Dv + d];
    }
    __syncthreads();

    if (tid < 256) {
        int r  = tid & 15;
        int l0 = (tid >> 4) << 2;
        float a0 = 0.f, a1 = 0.f, a2 = 0.f, a3 = 0.f;
#pragma unroll 8
        for (int d = 0; d < 256; ++d) {
            float  xv = xs[d * 17 + r];
            float4 wq = *(const float4*)&Wt[d * 68 + l0];
            a0 = fmaf(xv, wq.x, a0);
            a1 = fmaf(xv, wq.y, a1);
            a2 = fmaf(xv, wq.z, a2);
            a3 = fmaf(xv, wq.w, a3);
        }
        a0 *= lw[l0 + 0];
        a1 *= lw[l0 + 1];
        a2 *= lw[l0 + 2];
        a3 *= lw[l0 + 3];
        float* dst = g_xh + b * (Lv * Nv) + i0 + r;
        dst[(l0 + 0) * Nv] = a0;
        dst[(l0 + 1) * Nv] = a1;
        dst[(l0 + 2) * Nv] = a2;
        dst[(l0 + 3) * Nv] = a3;
        si2[(l0 + 0) * 16 + r] = pk2(-a0);
        si2[(l0 + 1) * 16 + r] = pk2(-a1);
        si2[(l0 + 2) * 16 + r] = pk2(-a2);
        si2[(l0 + 3) * 16 + r] = pk2(-a3);
    }
    __syncthreads();

    // ---------------- Device-wide barrier ----------------------------------
    if (tid == 0) {
        __threadfence();
        unsigned snap = *(volatile unsigned*)&g_release;   // BEFORE arriving
        unsigned old  = atomicAdd(&g_count, 1);
        if (old == gridDim.x - 1) {
            g_count = 0;
            __threadfence();
            atomicAdd(&g_release, 1);
        } else {
            while (*(volatile unsigned*)&g_release == snap) __nanosleep(32);
        }
        __threadfence();
    }
    __syncthreads();

    // ---------------- Phase B: stage sj, mainloop --------------------------
    const float* xh = g_xh + b * (Lv * Nv);
    for (int idx = tid; idx < (Lv * Nv) / 4; idx += 1024)
        ((float4*)sj)[idx] = ((const float4*)xh)[idx];
    __syncthreads();

    int w    = tid >> 5;
    int lane = tid & 31;
    int rg = w & 3;
    int jq = (w >> 2) & 3;
    int lh = w >> 4;
    int jbase = jq * 128 + lane * 4;
    int lb = lh * 32;

    const ull ABS2 = 0x7FFFFFFF7FFFFFFFull;
    ull a00 = 0, a01 = 0, a10 = 0, a11 = 0;
    ull a20 = 0, a21 = 0, a30 = 0, a31 = 0;

    const float* sjp = sj + (size_t)lb * Nv + jbase;
    const ull*   sip = si2 + lb * 16 + rg * 4;

    ulonglong2 jn = *(const ulonglong2*)sjp;
#pragma unroll
    for (int l = 0; l < 32; ++l) {
        ulonglong2 j01 = jn;
        if (l < 31) jn = *(const ulonglong2*)(sjp + (size_t)(l + 1) * Nv);
        ulonglong2 nab = *(const ulonglong2*)(sip + l * 16);
        ulonglong2 ncd = *(const ulonglong2*)(sip + l * 16 + 2);
        a00 = add2(a00, add2(j01.x, nab.x) & ABS2);
        a01 = add2(a01, add2(j01.y, nab.x) & ABS2);
        a10 = add2(a10, add2(j01.x, nab.y) & ABS2);
        a11 = add2(a11, add2(j01.y, nab.y) & ABS2);
        a20 = add2(a20, add2(j01.x, ncd.x) & ABS2);
        a21 = add2(a21, add2(j01.y, ncd.x) & ABS2);
        a30 = add2(a30, add2(j01.x, ncd.y) & ABS2);
        a31 = add2(a31, add2(j01.y, ncd.y) & ABS2);
    }

    float d[4][4];
    d[0][0] = lo2(a00); d[0][1] = hi2(a00); d[0][2] = lo2(a01); d[0][3] = hi2(a01);
    d[1][0] = lo2(a10); d[1][1] = hi2(a10); d[1][2] = lo2(a11); d[1][3] = hi2(a11);
    d[2][0] = lo2(a20); d[2][1] = hi2(a20); d[2][2] = lo2(a21); d[2][3] = hi2(a21);
    d[3][0] = lo2(a30); d[3][1] = hi2(a30); d[3][2] = lo2(a31); d[3][3] = hi2(a31);

    // ---------------- merge l-halves through psum ---------------------------
    if (lh == 0) {
#pragma unroll
        for (int r = 0; r < 4; ++r)
            *(float4*)&psum[(rg * 4 + r) * Nv + jbase] =
                make_float4(d[r][0], d[r][1], d[r][2], d[r][3]);
    }
    __syncthreads();
    if (lh == 1) {
#pragma unroll
        for (int r = 0; r < 4; ++r) {
            float4 p4 = *(const float4*)&psum[(rg * 4 + r) * Nv + jbase];
            p4.x += d[r][0]; p4.y += d[r][1]; p4.z += d[r][2]; p4.w += d[r][3];
            *(float4*)&psum[(rg * 4 + r) * Nv + jbase] = p4;
        }
    }
    __syncthreads();

    // ---------------- full-width epilogue: all 32 warps --------------------
    // warp -> (row = w>>1, half = w&1): 256 columns each.
    {
        int row  = w >> 1;
        int half = w & 1;
        int c0 = half * 256 + lane * 4;
        int c1 = c0 + 128;
        const float* prow = psum + row * Nv;

        float4 v0 = *(const float4*)&prow[c0];
        float4 v1 = *(const float4*)&prow[c1];
        // leaky relu
        v0.x = v0.x > 0.f ? v0.x : 0.01f * v0.x;
        v0.y = v0.y > 0.f ? v0.y : 0.01f * v0.y;
        v0.z = v0.z > 0.f ? v0.z : 0.01f * v0.z;
        v0.w = v0.w > 0.f ? v0.w : 0.01f * v0.w;
        v1.x = v1.x > 0.f ? v1.x : 0.01f * v1.x;
        v1.y = v1.y > 0.f ? v1.y : 0.01f * v1.y;
        v1.z = v1.z > 0.f ? v1.z : 0.01f * v1.z;
        v1.w = v1.w > 0.f ? v1.w : 0.01f * v1.w;

        float mr = fmaxf(fmaxf(fmaxf(v0.x, v0.y), fmaxf(v0.z, v0.w)),
                         fmaxf(fmaxf(v1.x, v1.y), fmaxf(v1.z, v1.w)));
#pragma unroll
        for (int o = 16; o; o >>= 1)
            mr = fmaxf(mr, __shfl_xor_sync(0xffffffffu, mr, o));
        if (lane == 0) red[row * 2 + half] = mr;
        __syncthreads();
        float M = fmaxf(red[row * 2], red[row * 2 + 1]);

        const float* arow = adjs + row * Nv;
        float4 A0 = *(const float4*)&arow[c0];
        float4 A1 = *(const float4*)&arow[c1];
        float4 e0, e1;
        e0.x = A0.x * __expf(v0.x - M);
        e0.y = A0.y * __expf(v0.y - M);
        e0.z = A0.z * __expf(v0.z - M);
        e0.w = A0.w * __expf(v0.w - M);
        e1.x = A1.x * __expf(v1.x - M);
        e1.y = A1.y * __expf(v1.y - M);
        e1.z = A1.z * __expf(v1.z - M);
        e1.w = A1.w * __expf(v1.w - M);

        float sr = e0.x + e0.y + e0.z + e0.w + e1.x + e1.y + e1.z + e1.w;
#pragma unroll
        for (int o = 16; o; o >>= 1)
            sr += __shfl_xor_sync(0xffffffffu, sr, o);
        if (lane == 0) red[32 + row * 2 + half] = sr;
        __syncthreads();
        float rs = 1.0f / (red[32 + row * 2] + red[32 + row * 2 + 1]);

        float* orow = out + (size_t)(b * Nv + i0 + row) * Nv;
        float4 o4;
        o4.x = e0.x * rs + 1e-10f; o4.y = e0.y * rs + 1e-10f;
        o4.z = e0.z * rs + 1e-10f; o4.w = e0.w * rs + 1e-10f;
        *(float4*)&orow[c0] = o4;
        o4.x = e1.x * rs + 1e-10f; o4.y = e1.y * rs + 1e-10f;
        o4.z = e1.z * rs + 1e-10f; o4.w = e1.w * rs + 1e-10f;
        *(float4*)&orow[c1] = o4;
    }
}

extern "C" void kernel_launch(void* const* d_in, const int* in_sizes, int n_in,
                              void* d_out, int out_size) {
    (void)in_sizes; (void)n_in; (void)out_size;
    const float* x   = (const float*)d_in[0];
    const float* adj = (const float*)d_in[1];
    const float* W   = (const float*)d_in[2];
    const float* lw  = (const float*)d_in[3];
    float* out = (float*)d_out;

    // sj 131072 + si2 8192 + psum 32768 + adjs 32768 + red 512
    const int smem = 131072 + 8192 + 32768 + 32768 + 512;   // 205312 B
    cudaFuncSetAttribute(fused_kernel,
                         cudaFuncAttributeMaxDynamicSharedMemorySize, smem);
    cudaFuncSetAttribute(fused_kernel,
                         cudaFuncAttributePreferredSharedMemoryCarveout,
                         cudaSharedmemCarveoutMaxShared);

    fused_kernel<<<Bv * (Nv / 16), 1024, smem>>>(x, adj, W, lw, out);
}